// round 2
// baseline (speedup 1.0000x reference)
#include <cuda_runtime.h>

#define HW    16384      // H*W
#define ROWS  4096       // B*C
#define CC    128
#define BB    32
#define TOPK  1638       // round(16384 * 0.1)
#define HID   8
#define NT    512
#define NB1   2048       // 11-bit digit bins (levels 0 and 1)
#define NB2   1024       // 10-bit final bins
#define CAP   4096       // candidate buffer capacity

__device__ float g_avg[ROWS];
__device__ float g_maxv[ROWS];

// Order-preserving float->uint key (larger float => larger key). 2 SASS ops.
__device__ __forceinline__ unsigned f2key(float f) {
    unsigned u = __float_as_uint(f);
    return u ^ ((unsigned)((int)u >> 31) | 0x80000000u);
}
__device__ __forceinline__ float key2f(unsigned k) {
    unsigned u = k ^ (((int)k < 0) ? 0x80000000u : 0xFFFFFFFFu);
    return __uint_as_float(u);
}

// Warp-aggregated histogram increment (d must be a valid bin index)
__device__ __forceinline__ void agg_add(int* h, int d) {
    unsigned m = __match_any_sync(0xffffffffu, d);
    if ((int)(threadIdx.x & 31) == __ffs((int)m) - 1)
        atomicAdd(&h[d], __popc(m));
}

// ---------------------------------------------------------------------------
// Hierarchical suffix-count select: finds bin b with s(b) >= rem > s(b+1),
// where s(b) = sum_{j>=b} h[j]. Writes sdigit, srem (=rem - s(b+1)), stotal.
// ---------------------------------------------------------------------------
template <int BPT>
__device__ __forceinline__ void suffix_select(const int* h, int rem,
                                              int* swarp, unsigned* sdigit,
                                              int* srem, int* stotal) {
    const int tid = threadIdx.x;
    const int lane = tid & 31, w = tid >> 5;
    const int base = tid * BPT;
    int loc[BPT];
    int tsum = 0;
#pragma unroll
    for (int i = 0; i < BPT; i++) { loc[i] = h[base + i]; tsum += loc[i]; }
    // inclusive suffix within warp (sum over lanes >= lane)
    int inc = tsum;
#pragma unroll
    for (int o = 1; o < 32; o <<= 1) {
        int v = __shfl_down_sync(0xffffffffu, inc, o);
        if (lane + o < 32) inc += v;
    }
    if (lane == 0) swarp[w] = inc;
    __syncthreads();
    if (tid == 0) {
        int run = 0;
        for (int i = 15; i >= 0; i--) { int t = swarp[i]; swarp[i] = run; run += t; }
        *stotal = run;
    }
    __syncthreads();
    int s_next = (inc - tsum) + swarp[w];   // suffix starting just past my bins
#pragma unroll
    for (int i = BPT - 1; i >= 0; i--) {
        int s = loc[i] + s_next;
        if (s >= rem && s_next < rem) { *sdigit = (unsigned)(base + i); *srem = rem - s_next; }
        s_next = s;
    }
    __syncthreads();
}

// ---------------------------------------------------------------------------
// Pass 1: per-(b,c) exact top-k mean + max, 3-level (11/11/10 bit) radix select
// ---------------------------------------------------------------------------
__global__ __launch_bounds__(NT) void topk_stats(const float* __restrict__ x) {
    __shared__ int      hist[NB1 + 1];     // +1 = trash bin for negatives
    __shared__ float    shist[NB2];
    __shared__ unsigned cand[CAP];
    __shared__ int      swarp[16];
    __shared__ unsigned sdigit;
    __shared__ int      srem, stotal, sncand;
    __shared__ float    sred[16];
    __shared__ unsigned ured[16];

    const int tid = threadIdx.x;
    const int lane = tid & 31, w = tid >> 5;
    const int row = blockIdx.x;
    const float4* xin = (const float4*)(x + (size_t)row * HW);

    for (int i = tid; i < NB1 + 1; i += NT) hist[i] = 0;
    if (tid == 0) sncand = 0;
    __syncthreads();

    // ---- pass 0: load, 11-bit histogram of non-negatives, row max ----
    unsigned lmax = 0;
#pragma unroll
    for (int i = 0; i < HW / (4 * NT); i++) {
        float4 v = xin[tid + i * NT];
        unsigned k0 = f2key(v.x), k1 = f2key(v.y), k2 = f2key(v.z), k3 = f2key(v.w);
        lmax = max(lmax, max(max(k0, k1), max(k2, k3)));
        agg_add(hist, ((int)k0 < 0) ? (int)(k0 >> 21) : NB1);
        agg_add(hist, ((int)k1 < 0) ? (int)(k1 >> 21) : NB1);
        agg_add(hist, ((int)k2 < 0) ? (int)(k2 >> 21) : NB1);
        agg_add(hist, ((int)k3 < 0) ? (int)(k3 >> 21) : NB1);
    }
#pragma unroll
    for (int o = 16; o; o >>= 1) lmax = max(lmax, __shfl_down_sync(0xffffffffu, lmax, o));
    if (lane == 0) ured[w] = lmax;
    __syncthreads();
    if (tid == 0) {
        unsigned m = 0;
        for (int i = 0; i < 16; i++) m = max(m, ured[i]);
        g_maxv[row] = key2f(m);
    }

    // ---- level-0 select (trash bin excluded) ----
    suffix_select<NB1 / NT>(hist, TOPK, swarp, &sdigit, &srem, &stotal);
    if (stotal < TOPK) {
        // rare exact fallback: fewer than TOPK non-negative values
        __syncthreads();
        for (int i = tid; i < NB1 + 1; i += NT) hist[i] = 0;
        __syncthreads();
#pragma unroll
        for (int i = 0; i < HW / (4 * NT); i++) {
            float4 v = xin[tid + i * NT];
            agg_add(hist, (int)(f2key(v.x) >> 21));
            agg_add(hist, (int)(f2key(v.y) >> 21));
            agg_add(hist, (int)(f2key(v.z) >> 21));
            agg_add(hist, (int)(f2key(v.w) >> 21));
        }
        __syncthreads();
        suffix_select<NB1 / NT>(hist, TOPK, swarp, &sdigit, &srem, &stotal);
    }
    const unsigned d0 = sdigit;
    const int rem1 = srem;

    // zero hist for level-1
    for (int i = tid; i < NB1; i += NT) hist[i] = 0;
    __syncthreads();

    // ---- pass 1: confirmed sum + candidate compaction + level-1 histogram ----
    float lsum = 0.f;
#pragma unroll
    for (int i = 0; i < HW / (4 * NT); i++) {
        float4 v = xin[tid + i * NT];
        float vv[4] = {v.x, v.y, v.z, v.w};
#pragma unroll
        for (int j = 0; j < 4; j++) {
            unsigned k = f2key(vv[j]);
            unsigned t = k >> 21;
            if (t > d0) lsum += vv[j];
            else if (t == d0) {
                int p = atomicAdd(&sncand, 1);
                if (p < CAP) cand[p] = k;
                atomicAdd(&hist[(k >> 10) & (NB1 - 1)], 1);
            }
        }
    }
    __syncthreads();
    const int n1 = sncand;
    suffix_select<NB1 / NT>(hist, rem1, swarp, &sdigit, &srem, &stotal);
    const unsigned d1 = sdigit;
    const int rem2 = srem;
    const unsigned P1 = (d0 << 11) | d1;     // 22-bit prefix

    // zero level-2 count + sum histograms
    for (int i = tid; i < NB2; i += NT) { hist[i] = 0; shist[i] = 0.f; }
    __syncthreads();

    // ---- pass 2: over candidates (or global fallback on overflow) ----
    if (n1 <= CAP) {
        for (int p = tid; p < n1; p += NT) {
            unsigned k = cand[p];
            unsigned t = k >> 10;
            if (t > P1) lsum += key2f(k);
            else if (t == P1) {
                atomicAdd(&hist[k & (NB2 - 1)], 1);
                atomicAdd(&shist[k & (NB2 - 1)], key2f(k));
            }
        }
    } else {
#pragma unroll
        for (int i = 0; i < HW / (4 * NT); i++) {
            float4 v = xin[tid + i * NT];
            float vv[4] = {v.x, v.y, v.z, v.w};
#pragma unroll
            for (int j = 0; j < 4; j++) {
                unsigned k = f2key(vv[j]);
                if ((k >> 21) == d0) {
                    unsigned t = k >> 10;
                    if (t > P1) lsum += vv[j];
                    else if (t == P1) {
                        atomicAdd(&hist[k & (NB2 - 1)], 1);
                        atomicAdd(&shist[k & (NB2 - 1)], vv[j]);
                    }
                }
            }
        }
    }
    __syncthreads();
    suffix_select<NB2 / NT>(hist, rem2, swarp, &sdigit, &srem, &stotal);
    const unsigned d2 = sdigit;
    const int ties = srem;

    // ---- sum of confirmed final-level values + block reduction ----
    float sa = 0.f;
    for (int b = tid; b < NB2; b += NT)
        if (b > (int)d2) sa += shist[b];
    float acc = lsum + sa;
#pragma unroll
    for (int o = 16; o; o >>= 1) acc += __shfl_down_sync(0xffffffffu, acc, o);
    if (lane == 0) sred[w] = acc;
    __syncthreads();
    if (tid == 0) {
        float s = 0.f;
        for (int i = 0; i < 16; i++) s += sred[i];
        unsigned T = (P1 << 10) | d2;
        g_avg[row] = (s + key2f(T) * (float)ties) / (float)TOPK;
    }
}

// ---------------------------------------------------------------------------
// Pass 2: fused tiny-MLP (recomputed per block, trivial) + elementwise scale
// ---------------------------------------------------------------------------
__global__ __launch_bounds__(256) void scale_kernel(const float* __restrict__ x,
                                                    float* __restrict__ y,
                                                    const float* __restrict__ w1,
                                                    const float* __restrict__ b1,
                                                    const float* __restrict__ w2,
                                                    const float* __restrict__ b2) {
    __shared__ float pool[2 * CC];
    __shared__ float hsh[2 * HID];
    __shared__ float ssc;
    const int row = blockIdx.x;
    const int b = row >> 7, c = row & (CC - 1);
    const int t = threadIdx.x;

    if (t < CC) pool[t] = g_avg[b * CC + t];
    else        pool[t] = g_maxv[b * CC + (t - CC)];
    __syncthreads();
    if (t < 2 * HID) {
        int j = t & (HID - 1);
        const float* p = pool + ((t < HID) ? 0 : CC);
        float s = b1[j];
#pragma unroll 8
        for (int i = 0; i < CC; i++) s += p[i] * w1[i * HID + j];
        hsh[t] = fmaxf(s, 0.f);
    }
    __syncthreads();
    if (t == 0) {
        float s = 2.f * b2[c];
#pragma unroll
        for (int j = 0; j < HID; j++) s += (hsh[j] + hsh[HID + j]) * w2[j * CC + c];
        ssc = 1.f / (1.f + __expf(-s));
    }
    __syncthreads();
    const float s = ssc;
    const float4* xi = (const float4*)(x + (size_t)row * HW);
    float4* yo = (float4*)(y + (size_t)row * HW);
#pragma unroll
    for (int i = 0; i < HW / (4 * 256); i++) {
        float4 v = xi[t + i * 256];
        v.x *= s; v.y *= s; v.z *= s; v.w *= s;
        yo[t + i * 256] = v;
    }
}

extern "C" void kernel_launch(void* const* d_in, const int* in_sizes, int n_in,
                              void* d_out, int out_size) {
    const float* x  = (const float*)d_in[0];
    const float* w1 = (const float*)d_in[1];
    const float* b1 = (const float*)d_in[2];
    const float* w2 = (const float*)d_in[3];
    const float* b2 = (const float*)d_in[4];
    float* y = (float*)d_out;

    topk_stats<<<ROWS, NT>>>(x);
    scale_kernel<<<ROWS, 256>>>(x, y, w1, b1, w2, b2);
}

// round 3
// speedup vs baseline: 1.4547x; 1.4547x over previous
#include <cuda_runtime.h>

#define HW    16384      // H*W
#define ROWS  4096       // B*C
#define CC    128
#define TOPK  1638       // round(16384 * 0.1)
#define HID   8
#define NT    512
#define NWARP (NT / 32)
#define NB    2048       // 11-bit bins (levels 1,2)
#define NB3   1024       // 10-bit final bins
#define WCAP  384        // per-warp candidate capacity
#define CAP   (NWARP * WCAP)   // 6144
#define T_LO  1.0f

__device__ float g_avg[ROWS];
__device__ float g_maxv[ROWS];

// Order-preserving float->uint key (larger float => larger key)
__device__ __forceinline__ unsigned f2key(float f) {
    unsigned u = __float_as_uint(f);
    return u ^ ((unsigned)((int)u >> 31) | 0x80000000u);
}
__device__ __forceinline__ float key2f(unsigned k) {
    unsigned u = k ^ (((int)k < 0) ? 0x80000000u : 0xFFFFFFFFu);
    return __uint_as_float(u);
}

// Warp-aggregated histogram increment; d == -1 means skip. Full-warp only.
__device__ __forceinline__ void agg_add(int* h, int d) {
    unsigned m = __match_any_sync(0xffffffffu, d);
    if (d >= 0 && (int)(threadIdx.x & 31) == __ffs((int)m) - 1)
        atomicAdd(&h[d], __popc(m));
}

// Suffix-count select: bin b with s(b) >= rem > s(b+1), s(b)=sum_{j>=b} h[j].
template <int BPT>
__device__ __forceinline__ void suffix_select(const int* h, int rem,
                                              int* swarp, unsigned* sdigit,
                                              int* srem) {
    const int tid = threadIdx.x, lane = tid & 31, w = tid >> 5;
    const int base = tid * BPT;
    int loc[BPT];
    int tsum = 0;
#pragma unroll
    for (int i = 0; i < BPT; i++) { loc[i] = h[base + i]; tsum += loc[i]; }
    int inc = tsum;
#pragma unroll
    for (int o = 1; o < 32; o <<= 1) {
        int v = __shfl_down_sync(0xffffffffu, inc, o);
        if (lane + o < 32) inc += v;
    }
    if (lane == 0) swarp[w] = inc;
    __syncthreads();
    if (tid == 0) {
        int run = 0;
        for (int i = NWARP - 1; i >= 0; i--) { int t = swarp[i]; swarp[i] = run; run += t; }
    }
    __syncthreads();
    int s_next = (inc - tsum) + swarp[w];
#pragma unroll
    for (int i = BPT - 1; i >= 0; i--) {
        int s = loc[i] + s_next;
        if (s >= rem && s_next < rem) { *sdigit = (unsigned)(base + i); *srem = rem - s_next; }
        s_next = s;
    }
    __syncthreads();
}

// ---------------------------------------------------------------------------
// Pass 1: per-(b,c) top-k mean + max. One DRAM sweep + select on candidates.
// ---------------------------------------------------------------------------
__global__ __launch_bounds__(NT) void topk_stats(const float* __restrict__ x) {
    __shared__ unsigned cand[CAP];        // 24 KB, per-warp segments
    __shared__ int      hist[NB];         // 8 KB
    __shared__ float    shist[NB3];       // 4 KB
    __shared__ int      wlen[NWARP];
    __shared__ int      swarp[NWARP];
    __shared__ unsigned sdigit;
    __shared__ int      srem, sok;
    __shared__ float    fred[NWARP];
    __shared__ int      ired[NWARP];

    const int tid = threadIdx.x, lane = tid & 31, w = tid >> 5;
    const int row = blockIdx.x;
    const float4* xin = (const float4*)(x + (size_t)row * HW);

    // zero candidate buffer (invalid slots read as key 0 = -inf float)
#pragma unroll
    for (int i = 0; i < CAP / NT; i++) cand[tid + i * NT] = 0u;
    __syncthreads();

    // ---- pass A: single sweep; row max + warp-local compaction of v > T_LO
    unsigned* wseg = cand + w * WCAP;
    int wcnt = 0;                         // warp-uniform (updated via ballot)
    float lmax = -3.402823466e38f;
#pragma unroll
    for (int i = 0; i < HW / (4 * NT); i++) {
        float4 v = xin[tid + i * NT];
        lmax = fmaxf(lmax, fmaxf(fmaxf(v.x, v.y), fmaxf(v.z, v.w)));
        float vv[4] = {v.x, v.y, v.z, v.w};
#pragma unroll
        for (int j = 0; j < 4; j++) {
            bool hit = vv[j] > T_LO;
            unsigned m = __ballot_sync(0xffffffffu, hit);
            if (hit) {
                int pos = wcnt + __popc(m & ((1u << lane) - 1u));
                if (pos < WCAP) wseg[pos] = f2key(vv[j]);
            }
            wcnt += __popc(m);
        }
    }
#pragma unroll
    for (int o = 16; o; o >>= 1) lmax = fmaxf(lmax, __shfl_down_sync(0xffffffffu, lmax, o));
    if (lane == 0) { fred[w] = lmax; wlen[w] = wcnt; }
    __syncthreads();
    if (tid == 0) {
        float m = fred[0];
        int nc = 0, ok = 1;
        for (int i = 0; i < NWARP; i++) {
            m = fmaxf(m, fred[i]);
            nc += wlen[i];
            if (wlen[i] > WCAP) ok = 0;
        }
        g_maxv[row] = m;
        sok = (ok && nc >= TOPK);
        srem = 0;
    }
    __syncthreads();

    float mean_num = 0.f;                 // accumulated on thread 0 at the end
    if (sok) {
        // ================= fast path: select among candidates ==============
        // L1: 11-bit digits (key >> 21)
        for (int i = tid; i < NB; i += NT) hist[i] = 0;
        __syncthreads();
#pragma unroll
        for (int i = 0; i < CAP / NT; i++)
            agg_add(hist, (int)(cand[tid + i * NT] >> 21));   // zeros -> bin 0, harmless
        __syncthreads();
        suffix_select<NB / NT>(hist, TOPK, swarp, &sdigit, &srem);
        const unsigned d0 = sdigit; const int rem1 = srem;

        // L2: next 11 bits among digit==d0
        for (int i = tid; i < NB; i += NT) hist[i] = 0;
        __syncthreads();
#pragma unroll
        for (int i = 0; i < CAP / NT; i++) {
            unsigned k = cand[tid + i * NT];
            agg_add(hist, ((k >> 21) == d0) ? (int)((k >> 10) & (NB - 1)) : -1);
        }
        __syncthreads();
        suffix_select<NB / NT>(hist, rem1, swarp, &sdigit, &srem);
        const unsigned P1 = (d0 << 11) | sdigit; const int rem2 = srem;

        // L3: final 10 bits; count+sum hist on sparse hits, sum of confirmed
        for (int i = tid; i < NB3; i += NT) { hist[i] = 0; shist[i] = 0.f; }
        __syncthreads();
        float lsum = 0.f;
#pragma unroll
        for (int i = 0; i < CAP / NT; i++) {
            unsigned k = cand[tid + i * NT];
            unsigned t = k >> 10;
            if (t > P1) lsum += key2f(k);
            else if (t == P1) {
                atomicAdd(&hist[k & (NB3 - 1)], 1);
                atomicAdd(&shist[k & (NB3 - 1)], key2f(k));
            }
        }
        __syncthreads();
        suffix_select<NB3 / NT>(hist, rem2, swarp, &sdigit, &srem);
        const unsigned d2 = sdigit; const int ties = srem;
        float sa = 0.f;
        for (int b = tid; b < NB3; b += NT)
            if (b > (int)d2) sa += shist[b];
        float acc = lsum + sa;
#pragma unroll
        for (int o = 16; o; o >>= 1) acc += __shfl_down_sync(0xffffffffu, acc, o);
        if (lane == 0) fred[w] = acc;
        __syncthreads();
        if (tid == 0) {
            float s = 0.f;
            for (int i = 0; i < NWARP; i++) s += fred[i];
            unsigned T = (P1 << 10) | d2;
            mean_num = s + key2f(T) * (float)ties;
            g_avg[row] = mean_num / (float)TOPK;
        }
    } else {
        // ======= exact fallback: bitwise binary search for k-th largest ====
        unsigned T = 0u;
        for (int bit = 31; bit >= 0; --bit) {
            const unsigned cT = T | (1u << bit);
            int c = 0;
#pragma unroll
            for (int i = 0; i < HW / (4 * NT); i++) {
                float4 v = xin[tid + i * NT];
                c += (f2key(v.x) >= cT) + (f2key(v.y) >= cT)
                   + (f2key(v.z) >= cT) + (f2key(v.w) >= cT);
            }
#pragma unroll
            for (int o = 16; o; o >>= 1) c += __shfl_down_sync(0xffffffffu, c, o);
            if (lane == 0) ired[w] = c;
            __syncthreads();
            if (tid == 0) {
                int s = 0;
                for (int i = 0; i < NWARP; i++) s += ired[i];
                srem = s;
            }
            __syncthreads();
            if (srem >= TOPK) T = cT;
            __syncthreads();
        }
        float ls = 0.f; int lc = 0;
#pragma unroll
        for (int i = 0; i < HW / (4 * NT); i++) {
            float4 v = xin[tid + i * NT];
            float vv[4] = {v.x, v.y, v.z, v.w};
#pragma unroll
            for (int j = 0; j < 4; j++) {
                unsigned k = f2key(vv[j]);
                if (k > T) { ls += vv[j]; lc++; }
            }
        }
#pragma unroll
        for (int o = 16; o; o >>= 1) {
            ls += __shfl_down_sync(0xffffffffu, ls, o);
            lc += __shfl_down_sync(0xffffffffu, lc, o);
        }
        if (lane == 0) { fred[w] = ls; ired[w] = lc; }
        __syncthreads();
        if (tid == 0) {
            float s = 0.f; int c = 0;
            for (int i = 0; i < NWARP; i++) { s += fred[i]; c += ired[i]; }
            g_avg[row] = (s + key2f(T) * (float)(TOPK - c)) / (float)TOPK;
        }
    }
}

// ---------------------------------------------------------------------------
// Pass 2: fused tiny-MLP (recomputed per block) + streaming elementwise scale
// ---------------------------------------------------------------------------
__global__ __launch_bounds__(256) void scale_kernel(const float* __restrict__ x,
                                                    float* __restrict__ y,
                                                    const float* __restrict__ w1,
                                                    const float* __restrict__ b1,
                                                    const float* __restrict__ w2,
                                                    const float* __restrict__ b2) {
    __shared__ float pool[2 * CC];
    __shared__ float hsh[2 * HID];
    __shared__ float ssc;
    const int row = blockIdx.x;
    const int b = row >> 7, c = row & (CC - 1);
    const int t = threadIdx.x;

    if (t < CC) pool[t] = g_avg[b * CC + t];
    else        pool[t] = g_maxv[b * CC + (t - CC)];
    __syncthreads();
    if (t < 2 * HID) {
        int j = t & (HID - 1);
        const float* p = pool + ((t < HID) ? 0 : CC);
        float s = b1[j];
#pragma unroll 8
        for (int i = 0; i < CC; i++) s += p[i] * w1[i * HID + j];
        hsh[t] = fmaxf(s, 0.f);
    }
    __syncthreads();
    if (t == 0) {
        float s = 2.f * b2[c];
#pragma unroll
        for (int j = 0; j < HID; j++) s += (hsh[j] + hsh[HID + j]) * w2[j * CC + c];
        ssc = 1.f / (1.f + __expf(-s));
    }
    __syncthreads();
    const float s = ssc;
    const float4* xi = (const float4*)(x + (size_t)row * HW);
    float4* yo = (float4*)(y + (size_t)row * HW);
#pragma unroll
    for (int i = 0; i < HW / (4 * 256); i++) {
        float4 v = __ldcs(&xi[t + i * 256]);
        v.x *= s; v.y *= s; v.z *= s; v.w *= s;
        __stcs(&yo[t + i * 256], v);
    }
}

extern "C" void kernel_launch(void* const* d_in, const int* in_sizes, int n_in,
                              void* d_out, int out_size) {
    const float* x  = (const float*)d_in[0];
    const float* w1 = (const float*)d_in[1];
    const float* b1 = (const float*)d_in[2];
    const float* w2 = (const float*)d_in[3];
    const float* b2 = (const float*)d_in[4];
    float* y = (float*)d_out;

    topk_stats<<<ROWS, NT>>>(x);
    scale_kernel<<<ROWS, 256>>>(x, y, w1, b1, w2, b2);
}